// round 14
// baseline (speedup 1.0000x reference)
#include <cuda_runtime.h>
#include <cuda_fp16.h>
#include <cstdint>

#define OUT_HALF 16777216           // 8*64*128*256
#define LDH   264                   // half pitch for 64x256 half buffers

#define BUF1_OFF 0                  // 33792 B : LN(x_kv) -> later Q
#define BUF2_OFF 33792              // 33792 B : LN(x_q) -> later AO
#define BUF3_OFF 67584              // 33792 B : [K|V]
#define SMEM_BYTES 101376

// ------ folded weights, paired-fragment-major: uint4 = frags (2*n4, 2*n4+1) --------
// index = (k16*16 + n4)*32 + lane ; .xy = mma b0,b1 of frag 2*n4 ; .zw = frag 2*n4+1
__device__ uint4 g_Wq[2][8192];     // gamma-q folded, * (1/sqrt(32))*log2(e)
__device__ uint4 g_Wkv[2][8192];    // [K|V], gamma-kv folded
__device__ uint4 g_Wo[2][8192];
__device__ float g_bq[2][256];
__device__ float g_bkv[2][256];

#define QS2 (0.17677669529663687f * 1.4426950408889634f)

// ---------------- PTX primitives ----------------------------------------------------
__device__ __forceinline__ uint32_t smem_u32(const void* p) {
    uint32_t a;
    asm("{ .reg .u64 t; cvta.to.shared.u64 t, %1; cvt.u32.u64 %0, t; }" : "=r"(a) : "l"(p));
    return a;
}
__device__ __forceinline__ void ldsm4(uint32_t* r, uint32_t a) {
    asm volatile("ldmatrix.sync.aligned.m8n8.x4.shared.b16 {%0,%1,%2,%3}, [%4];"
                 : "=r"(r[0]), "=r"(r[1]), "=r"(r[2]), "=r"(r[3]) : "r"(a));
}
__device__ __forceinline__ void ldsm4t(uint32_t* r, uint32_t a) {
    asm volatile("ldmatrix.sync.aligned.m8n8.x4.trans.shared.b16 {%0,%1,%2,%3}, [%4];"
                 : "=r"(r[0]), "=r"(r[1]), "=r"(r[2]), "=r"(r[3]) : "r"(a));
}
__device__ __forceinline__ void mma16816(float* c, const uint32_t* a, uint32_t b0, uint32_t b1) {
    asm volatile("mma.sync.aligned.m16n8k16.row.col.f32.f16.f16.f32 "
                 "{%0,%1,%2,%3}, {%4,%5,%6,%7}, {%8,%9}, {%0,%1,%2,%3};"
                 : "+f"(c[0]), "+f"(c[1]), "+f"(c[2]), "+f"(c[3])
                 : "r"(a[0]), "r"(a[1]), "r"(a[2]), "r"(a[3]), "r"(b0), "r"(b1));
}
__device__ __forceinline__ float ex2f(float x) {
    float y; asm("ex2.approx.f32 %0, %1;" : "=f"(y) : "f"(x)); return y;
}
__device__ __forceinline__ uint32_t h2u(float a, float b) {
    __half2 h = __floats2half2_rn(a, b);
    return *reinterpret_cast<uint32_t*>(&h);
}

// ---------------- single prep kernel ------------------------------------------------
__global__ void prep_all(const float* __restrict__ gq0, const float* __restrict__ gkv0,
                         const float* __restrict__ gq1, const float* __restrict__ gkv1,
                         const float* __restrict__ bqn0, const float* __restrict__ bkvn0,
                         const float* __restrict__ bqn1, const float* __restrict__ bkvn1,
                         const float* __restrict__ Wq0, const float* __restrict__ bq0,
                         const float* __restrict__ Wk0, const float* __restrict__ bk0,
                         const float* __restrict__ Wv0, const float* __restrict__ bv0,
                         const float* __restrict__ Wo0,
                         const float* __restrict__ Wq1, const float* __restrict__ bq1,
                         const float* __restrict__ Wk1, const float* __restrict__ bk1,
                         const float* __restrict__ Wv1, const float* __restrict__ bv1,
                         const float* __restrict__ Wo1) {
    int gid = blockIdx.x * blockDim.x + threadIdx.x;
    if (gid < 98304) {              // 2 branches x 3 mats x 512 frags x 32 lanes
        int br = gid / 49152;
        int rem = gid - br * 49152;
        int mat = rem >> 14;        // 0=Wq 1=Wkv 2=Wo
        int f = rem & 16383;
        int fid = f >> 5;           // frag id 0..511
        int lane = f & 31;
        int k16 = fid >> 5;         // 0..15
        int n8 = fid & 31;          // 0..31
        int c = n8 * 8 + (lane >> 2);
        int kb = k16 * 16 + (lane & 3) * 2;
        float v0, v1, v2, v3;
        if (mat == 0) {
            const float* gq = br ? gq1 : gq0; const float* Wq = br ? Wq1 : Wq0;
            v0 = gq[kb]     * Wq[kb * 256 + c]       * QS2;
            v1 = gq[kb + 1] * Wq[(kb + 1) * 256 + c] * QS2;
            v2 = gq[kb + 8] * Wq[(kb + 8) * 256 + c] * QS2;
            v3 = gq[kb + 9] * Wq[(kb + 9) * 256 + c] * QS2;
        } else if (mat == 1) {
            const float* gkv = br ? gkv1 : gkv0;
            const float* Wk = br ? Wk1 : Wk0; const float* Wv = br ? Wv1 : Wv0;
            const float* Wm = (c < 128) ? Wk : Wv;
            int cc = c & 127;
            v0 = gkv[kb]     * Wm[kb * 128 + cc];
            v1 = gkv[kb + 1] * Wm[(kb + 1) * 128 + cc];
            v2 = gkv[kb + 8] * Wm[(kb + 8) * 128 + cc];
            v3 = gkv[kb + 9] * Wm[(kb + 9) * 128 + cc];
        } else {
            const float* Wo = br ? Wo1 : Wo0;
            v0 = Wo[kb * 256 + c];
            v1 = Wo[(kb + 1) * 256 + c];
            v2 = Wo[(kb + 8) * 256 + c];
            v3 = Wo[(kb + 9) * 256 + c];
        }
        uint4* dst4 = (mat == 0) ? g_Wq[br] : (mat == 1) ? g_Wkv[br] : g_Wo[br];
        uint32_t* d32 = reinterpret_cast<uint32_t*>(dst4);
        int n4 = n8 >> 1;
        int base = ((k16 * 16 + n4) * 32 + lane) * 4 + (n8 & 1) * 2;
        d32[base]     = h2u(v0, v1);
        d32[base + 1] = h2u(v2, v3);
    } else if (gid < 99328) {
        int t = gid - 98304;
        int br = t >> 9, tt = t & 511;
        const float* bqn = br ? bqn1 : bqn0; const float* bkvn = br ? bkvn1 : bkvn0;
        const float* Wq = br ? Wq1 : Wq0; const float* Wk = br ? Wk1 : Wk0;
        const float* Wv = br ? Wv1 : Wv0;
        const float* bq = br ? bq1 : bq0; const float* bk = br ? bk1 : bk0;
        const float* bv = br ? bv1 : bv0;
        if (tt < 256) {
            float a = bq[tt];
            for (int k = 0; k < 256; ++k) a += bqn[k] * Wq[k * 256 + tt];
            g_bq[br][tt] = a * QS2;
        } else if (tt < 384) {
            int c = tt - 256; float a = bk[c];
            for (int k = 0; k < 256; ++k) a += bkvn[k] * Wk[k * 128 + c];
            g_bkv[br][c] = a;
        } else {
            int c = tt - 384; float a = bv[c];
            for (int k = 0; k < 256; ++k) a += bkvn[k] * Wv[k * 128 + c];
            g_bkv[br][c + 128] = a;
        }
    }
}

// ---------------- main fused kernel: 1 CTA = 1 sequence, 1 branch -------------------
__global__ void __launch_bounds__(256, 2)
fusion_kernel(const float* __restrict__ xspec, const float* __restrict__ xspat,
              const float* __restrict__ bo0, const float* __restrict__ bo1,
              const float* __restrict__ gate0, const float* __restrict__ gate1,
              float* __restrict__ out) {
    extern __shared__ char smc[];
    __half* buf1 = reinterpret_cast<__half*>(smc + BUF1_OFF);   // LN(xkv) -> Q
    __half* buf2 = reinterpret_cast<__half*>(smc + BUF2_OFF);   // LN(xq) -> AO
    __half* buf3 = reinterpret_cast<__half*>(smc + BUF3_OFF);   // K|V

    int tid = threadIdx.x, w = tid >> 5, lane = tid & 31;
    int br = blockIdx.x & 1;              // interleaved: CTA pairs share x tiles in L2
    int bc = blockIdx.x >> 1;
    int b = bc >> 7, c = bc & 127;
    int cbase = (b * 8192 + c) * 256;

    const float* xq  = br ? xspat : xspec;
    const float* xkv = br ? xspec : xspat;
    const float* bo  = br ? bo1 : bo0;
    float gv = br ? gate1[0] : gate0[0];
    float sg = 1.0f / (1.0f + __expf(-gv));
    float* outb = out + (br ? OUT_HALF : 0);

    // ---------- LN: 64 rows -> half buffer ----------
    auto ln_rows = [&](__half* dst, const float* __restrict__ src) {
        for (int r = w; r < 64; r += 8) {
            const float* rp = src + cbase + r * 32768;
            float4 u = *reinterpret_cast<const float4*>(rp + lane * 8);
            float4 v = *reinterpret_cast<const float4*>(rp + lane * 8 + 4);
            float s = u.x + u.y + u.z + u.w + v.x + v.y + v.z + v.w;
            float q = u.x * u.x + u.y * u.y + u.z * u.z + u.w * u.w +
                      v.x * v.x + v.y * v.y + v.z * v.z + v.w * v.w;
#pragma unroll
            for (int o = 16; o; o >>= 1) {
                s += __shfl_xor_sync(0xffffffffu, s, o);
                q += __shfl_xor_sync(0xffffffffu, q, o);
            }
            float mu = s * (1.0f / 256.0f);
            float rs = rsqrtf(q * (1.0f / 256.0f) - mu * mu + 1e-5f);
            uint4 pk;
            uint32_t* ph = reinterpret_cast<uint32_t*>(&pk);
            ph[0] = h2u((u.x - mu) * rs, (u.y - mu) * rs);
            ph[1] = h2u((u.z - mu) * rs, (u.w - mu) * rs);
            ph[2] = h2u((v.x - mu) * rs, (v.y - mu) * rs);
            ph[3] = h2u((v.z - mu) * rs, (v.w - mu) * rs);
            *reinterpret_cast<uint4*>(dst + r * LDH + lane * 8) = pk;
        }
    };

    // ---- GEMM: C[64x256] = A @ W + bias; B triple-buffered (prefetch distance 2) ----
    auto gemm64 = [&](const __half* Abuf, const uint4* __restrict__ WF,
                      const float* __restrict__ bias, __half* dsth, int MODE, int SYNC) {
        int m0 = (w & 1) * 32, n0 = (w >> 1) * 64;
        int l15 = lane & 15, lhi = (lane >> 4) * 8;
        uint32_t aBase = smem_u32(Abuf) + ((m0 + l15) * LDH + lhi) * 2;
        const uint4* Wl = WF + (w >> 1) * 128 + lane;   // n4 base * 32 lanes

        float acc[16][4];
#pragma unroll
        for (int i = 0; i < 16; ++i)
#pragma unroll
            for (int j = 0; j < 4; ++j) acc[i][j] = 0.0f;

        uint4 B[3][4];
#pragma unroll
        for (int i = 0; i < 4; ++i) B[0][i] = Wl[i * 32];
#pragma unroll
        for (int i = 0; i < 4; ++i) B[1][i] = Wl[512 + i * 32];

#pragma unroll
        for (int k16 = 0; k16 < 16; ++k16) {
            const int cur = k16 % 3;
            if (k16 < 14) {
                const int pf = (k16 + 2) % 3;
#pragma unroll
                for (int i = 0; i < 4; ++i)
                    B[pf][i] = Wl[(k16 + 2) * 512 + i * 32];
            }
            uint32_t a0[4], a1[4];
            uint32_t ak = aBase + (k16 * 16) * 2;
            ldsm4(a0, ak);
            ldsm4(a1, ak + 16 * LDH * 2);
#pragma unroll
            for (int ng = 0; ng < 4; ++ng) {
                mma16816(acc[ng * 2],     a0, B[cur][ng].x, B[cur][ng].y);
                mma16816(acc[ng * 2 + 1], a0, B[cur][ng].z, B[cur][ng].w);
                mma16816(acc[8 + ng * 2],     a1, B[cur][ng].x, B[cur][ng].y);
                mma16816(acc[8 + ng * 2 + 1], a1, B[cur][ng].z, B[cur][ng].w);
            }
        }
        if (SYNC) __syncthreads();

        int g = lane >> 2, c2 = (lane & 3) * 2;
        if (MODE == 0) {
#pragma unroll
            for (int nt = 0; nt < 8; ++nt) {
                int col = n0 + nt * 8 + c2;
                float2 bb = *reinterpret_cast<const float2*>(bias + col);
#pragma unroll
                for (int mi = 0; mi < 2; ++mi) {
                    float* a4 = acc[mi * 8 + nt];
                    uint32_t h0 = h2u(a4[0] + bb.x, a4[1] + bb.y);
                    uint32_t h1 = h2u(a4[2] + bb.x, a4[3] + bb.y);
                    *reinterpret_cast<uint32_t*>(dsth + (m0 + mi * 16 + g) * LDH + col) = h0;
                    *reinterpret_cast<uint32_t*>(dsth + (m0 + mi * 16 + 8 + g) * LDH + col) = h1;
                }
            }
        } else {
#pragma unroll
            for (int nt = 0; nt < 8; ++nt) {
                int col = n0 + nt * 8 + c2;
                float2 bb = *reinterpret_cast<const float2*>(bias + col);
#pragma unroll
                for (int mi = 0; mi < 2; ++mi) {
                    float* a4 = acc[mi * 8 + nt];
#pragma unroll
                    for (int hrow = 0; hrow < 2; ++hrow) {
                        int row = m0 + mi * 16 + hrow * 8 + g;
                        int off = cbase + row * 32768 + col;
                        float2 x = *reinterpret_cast<const float2*>(xq + off);
                        float2 o;
                        o.x = x.x + sg * (a4[hrow * 2 + 0] + bb.x);
                        o.y = x.y + sg * (a4[hrow * 2 + 1] + bb.y);
                        *reinterpret_cast<float2*>(outb + off) = o;
                    }
                }
            }
        }
    };

    // ================= pipeline (4 CTA barriers total) =================
    ln_rows(buf1, xkv);
    ln_rows(buf2, xq);
    __syncthreads();                                       // (1) LN complete
    gemm64(buf1, g_Wkv[br], g_bkv[br], buf3, 0, 0);        // KV: no barriers at all
    gemm64(buf2, g_Wq[br], g_bq[br], buf1, 0, 1);          // Q:  (2) guard buf1 reuse
    __syncthreads();                                       // (3) Q/KV visible to all

    // ===== attention: K/V frags shared per query-head pair; 1/sum folded into AO ====
    {
        int rows0 = (w & 3) * 16;
        int l15 = lane & 15, lhi = (lane >> 4) * 8;
        int g = lane >> 2, c2 = (lane & 3) * 2;
        uint32_t q_base = smem_u32(buf1) + ((rows0 + l15) * LDH + lhi) * 2;
        uint32_t k_base = smem_u32(buf3) + (l15 * LDH + lhi) * 2;

#pragma unroll
        for (int hpi = 0; hpi < 2; ++hpi) {
            int hp = (w >> 2) * 2 + hpi;           // kv head 0..3
            int ko = hp * 32, vo = 128 + hp * 32;
            uint32_t kr[4][2][4];
#pragma unroll
            for (int tb = 0; tb < 4; ++tb)
#pragma unroll
                for (int db = 0; db < 2; ++db)
                    ldsm4(kr[tb][db], k_base + (tb * 16 * LDH + ko + db * 16) * 2);

            uint32_t aP[2][4][4];
            float inv0[2], inv1[2];
#pragma unroll
            for (int qh = 0; qh < 2; ++qh) {
                int qo = (hp * 2 + qh) * 32;
                uint32_t aQ[2][4];
                ldsm4(aQ[0], q_base + qo * 2);
                ldsm4(aQ[1], q_base + (qo + 16) * 2);
                float sc[8][4];
#pragma unroll
                for (int i = 0; i < 8; ++i)
#pragma unroll
                    for (int j = 0; j < 4; ++j) sc[i][j] = 0.0f;
#pragma unroll
                for (int tb = 0; tb < 4; ++tb)
#pragma unroll
                    for (int db = 0; db < 2; ++db) {
                        mma16816(sc[2 * tb],     aQ[db], kr[tb][db][0], kr[tb][db][2]);
                        mma16816(sc[2 * tb + 1], aQ[db], kr[tb][db][1], kr[tb][db][3]);
                    }
                float mx0 = -3.4e38f, mx1 = -3.4e38f;
#pragma unroll
                for (int nt = 0; nt < 8; ++nt) {
                    mx0 = fmaxf(mx0, fmaxf(sc[nt][0], sc[nt][1]));
                    mx1 = fmaxf(mx1, fmaxf(sc[nt][2], sc[nt][3]));
                }
                mx0 = fmaxf(mx0, __shfl_xor_sync(0xffffffffu, mx0, 1));
                mx0 = fmaxf(mx0, __shfl_xor_sync(0xffffffffu, mx0, 2));
                mx1 = fmaxf(mx1, __shfl_xor_sync(0xffffffffu, mx1, 1));
                mx1 = fmaxf(mx1, __shfl_xor_sync(0xffffffffu, mx1, 2));
                float s0 = 0.0f, s1 = 0.0f;
#pragma unroll
                for (int nt = 0; nt < 8; ++nt) {
                    sc[nt][0] = ex2f(sc[nt][0] - mx0); s0 += sc[nt][0];
                    sc[nt][1] = ex2f(sc[nt][1] - mx0); s0 += sc[nt][1];
                    sc[nt][2] = ex2f(sc[nt][2] - mx1); s1 += sc[nt][2];
                    sc[nt][3] = ex2f(sc[nt][3] - mx1); s1 += sc[nt][3];
                }
                s0 += __shfl_xor_sync(0xffffffffu, s0, 1);
                s0 += __shfl_xor_sync(0xffffffffu, s0, 2);
                s1 += __shfl_xor_sync(0xffffffffu, s1, 1);
                s1 += __shfl_xor_sync(0xffffffffu, s1, 2);
                inv0[qh] = 1.0f / s0;
                inv1[qh] = 1.0f / s1;
                // P stored UN-normalized (exp in (0,1]); 1/sum applied at AO pack
#pragma unroll
                for (int kf = 0; kf < 4; ++kf) {
                    float* p0 = sc[2 * kf];
                    float* p1 = sc[2 * kf + 1];
                    aP[qh][kf][0] = h2u(p0[0], p0[1]);
                    aP[qh][kf][1] = h2u(p0[2], p0[3]);
                    aP[qh][kf][2] = h2u(p1[0], p1[1]);
                    aP[qh][kf][3] = h2u(p1[2], p1[3]);
                }
            }
            uint32_t vr[4][2][4];
#pragma unroll
            for (int tb = 0; tb < 4; ++tb)
#pragma unroll
                for (int db = 0; db < 2; ++db)
                    ldsm4t(vr[tb][db], k_base + (tb * 16 * LDH + vo + db * 16) * 2);
#pragma unroll
            for (int qh = 0; qh < 2; ++qh) {
                int qo = (hp * 2 + qh) * 32;
                float ao[4][4];
#pragma unroll
                for (int i = 0; i < 4; ++i)
#pragma unroll
                    for (int j = 0; j < 4; ++j) ao[i][j] = 0.0f;
#pragma unroll
                for (int kb = 0; kb < 4; ++kb)
#pragma unroll
                    for (int db = 0; db < 2; ++db) {
                        mma16816(ao[2 * db],     aP[qh][kb], vr[kb][db][0], vr[kb][db][1]);
                        mma16816(ao[2 * db + 1], aP[qh][kb], vr[kb][db][2], vr[kb][db][3]);
                    }
                float i0 = inv0[qh], i1 = inv1[qh];
#pragma unroll
                for (int dn = 0; dn < 4; ++dn) {
                    int col = qo + dn * 8 + c2;
                    *reinterpret_cast<uint32_t*>(buf2 + (rows0 + g) * LDH + col) =
                        h2u(ao[dn][0] * i0, ao[dn][1] * i0);
                    *reinterpret_cast<uint32_t*>(buf2 + (rows0 + 8 + g) * LDH + col) =
                        h2u(ao[dn][2] * i1, ao[dn][3] * i1);
                }
            }
        }
    }
    __syncthreads();                                       // (4) AO visible

    // ================= O projection + residual epilogue =================
    gemm64(buf2, g_Wo[br], bo, nullptr, 1, 0);
}

// ---------------- host launcher -------------------------------------------------------
extern "C" void kernel_launch(void* const* d_in, const int* in_sizes, int n_in,
                              void* d_out, int out_size) {
    const float* xspec = (const float*)d_in[0];
    const float* xspat = (const float*)d_in[1];
    const float* lsqg  = (const float*)d_in[2];
    const float* lsqb  = (const float*)d_in[3];
    const float* lskvg = (const float*)d_in[4];
    const float* lskvb = (const float*)d_in[5];
    const float* ltqg  = (const float*)d_in[6];
    const float* ltqb  = (const float*)d_in[7];
    const float* ltkvg = (const float*)d_in[8];
    const float* ltkvb = (const float*)d_in[9];
    const float* Wq0 = (const float*)d_in[10]; const float* bq0 = (const float*)d_in[11];
    const float* Wk0 = (const float*)d_in[12]; const float* bk0 = (const float*)d_in[13];
    const float* Wv0 = (const float*)d_in[14]; const float* bv0 = (const float*)d_in[15];
    const float* Wo0 = (const float*)d_in[16]; const float* bo0 = (const float*)d_in[17];
    const float* Wq1 = (const float*)d_in[18]; const float* bq1 = (const float*)d_in[19];
    const float* Wk1 = (const float*)d_in[20]; const float* bk1 = (const float*)d_in[21];
    const float* Wv1 = (const float*)d_in[22]; const float* bv1 = (const float*)d_in[23];
    const float* Wo1 = (const float*)d_in[24]; const float* bo1 = (const float*)d_in[25];
    const float* g0  = (const float*)d_in[26];
    const float* g1  = (const float*)d_in[27];
    float* out = (float*)d_out;

    // branch 0 (s2t): q-norm=spec_q, kv-norm=spat_kv; branch 1 (t2s): q-norm=spat_q, kv-norm=spec_kv
    prep_all<<<388, 256>>>(lsqg, ltkvg, ltqg, lskvg,
                           lsqb, ltkvb, ltqb, lskvb,
                           Wq0, bq0, Wk0, bk0, Wv0, bv0, Wo0,
                           Wq1, bq1, Wk1, bk1, Wv1, bv1, Wo1);

    cudaFuncSetAttribute(fusion_kernel, cudaFuncAttributeMaxDynamicSharedMemorySize, SMEM_BYTES);
    fusion_kernel<<<2048, 256, SMEM_BYTES>>>(xspec, xspat, bo0, bo1, g0, g1, out);
}

// round 15
// speedup vs baseline: 1.0442x; 1.0442x over previous
#include <cuda_runtime.h>
#include <cuda_fp16.h>
#include <cstdint>

#define OUT_HALF 16777216           // 8*64*128*256
#define LDH   264                   // half pitch for 64x256 half buffers

#define BUF1_OFF 0                  // 33792 B : LN(x_kv) -> [K|V]
#define BUF2_OFF 33792              // 33792 B : LN(x_q) -> Q -> AO
#define SMEM_BYTES 67584

// ---------------- folded weights in mma-fragment-major layout -----------------------
// frag id = k16*32 + n8  (k16 in [0,16), n8 in [0,32)); per frag: 32 lanes x uint2.
// lane l holds halves { W[k16*16 + 2(l%4)][c], W[..+1][c], W[k16*16+8+2(l%4)][c], W[..+1][c] }
// with c = n8*8 + l/4  -> uint2 = (b0, b1) mma B operand registers, directly.
__device__ uint2 g_Wq[2][16384];    // gamma-q folded, * (1/sqrt(32))*log2(e)
__device__ uint2 g_Wkv[2][16384];   // [K|V], gamma-kv folded
__device__ uint2 g_Wo[2][16384];
__device__ float g_bq[2][256];
__device__ float g_bkv[2][256];

#define QS2 (0.17677669529663687f * 1.4426950408889634f)

// ---------------- PTX primitives ----------------------------------------------------
__device__ __forceinline__ uint32_t smem_u32(const void* p) {
    uint32_t a;
    asm("{ .reg .u64 t; cvta.to.shared.u64 t, %1; cvt.u32.u64 %0, t; }" : "=r"(a) : "l"(p));
    return a;
}
__device__ __forceinline__ void ldsm4(uint32_t* r, uint32_t a) {
    asm volatile("ldmatrix.sync.aligned.m8n8.x4.shared.b16 {%0,%1,%2,%3}, [%4];"
                 : "=r"(r[0]), "=r"(r[1]), "=r"(r[2]), "=r"(r[3]) : "r"(a));
}
__device__ __forceinline__ void ldsm4t(uint32_t* r, uint32_t a) {
    asm volatile("ldmatrix.sync.aligned.m8n8.x4.trans.shared.b16 {%0,%1,%2,%3}, [%4];"
                 : "=r"(r[0]), "=r"(r[1]), "=r"(r[2]), "=r"(r[3]) : "r"(a));
}
__device__ __forceinline__ void mma16816(float* c, const uint32_t* a, uint32_t b0, uint32_t b1) {
    asm volatile("mma.sync.aligned.m16n8k16.row.col.f32.f16.f16.f32 "
                 "{%0,%1,%2,%3}, {%4,%5,%6,%7}, {%8,%9}, {%0,%1,%2,%3};"
                 : "+f"(c[0]), "+f"(c[1]), "+f"(c[2]), "+f"(c[3])
                 : "r"(a[0]), "r"(a[1]), "r"(a[2]), "r"(a[3]), "r"(b0), "r"(b1));
}
__device__ __forceinline__ float ex2f(float x) {
    float y; asm("ex2.approx.f32 %0, %1;" : "=f"(y) : "f"(x)); return y;
}
__device__ __forceinline__ uint32_t h2u(float a, float b) {
    __half2 h = __floats2half2_rn(a, b);
    return *reinterpret_cast<uint32_t*>(&h);
}

// ---------------- single prep kernel ------------------------------------------------
__global__ void prep_all(const float* __restrict__ gq0, const float* __restrict__ gkv0,
                         const float* __restrict__ gq1, const float* __restrict__ gkv1,
                         const float* __restrict__ bqn0, const float* __restrict__ bkvn0,
                         const float* __restrict__ bqn1, const float* __restrict__ bkvn1,
                         const float* __restrict__ Wq0, const float* __restrict__ bq0,
                         const float* __restrict__ Wk0, const float* __restrict__ bk0,
                         const float* __restrict__ Wv0, const float* __restrict__ bv0,
                         const float* __restrict__ Wo0,
                         const float* __restrict__ Wq1, const float* __restrict__ bq1,
                         const float* __restrict__ Wk1, const float* __restrict__ bk1,
                         const float* __restrict__ Wv1, const float* __restrict__ bv1,
                         const float* __restrict__ Wo1) {
    int gid = blockIdx.x * blockDim.x + threadIdx.x;
    if (gid < 98304) {              // 2 branches x 3 mats x 512 frags x 32 lanes
        int br = gid / 49152;
        int rem = gid - br * 49152;
        int mat = rem >> 14;        // 0=Wq 1=Wkv 2=Wo
        int f = rem & 16383;
        int fid = f >> 5;           // frag id 0..511
        int lane = f & 31;
        int k16 = fid >> 5;         // 0..15
        int n8 = fid & 31;          // 0..31
        int c = n8 * 8 + (lane >> 2);
        int kb = k16 * 16 + (lane & 3) * 2;
        float v0, v1, v2, v3;
        if (mat == 0) {
            const float* gq = br ? gq1 : gq0; const float* Wq = br ? Wq1 : Wq0;
            v0 = gq[kb]     * Wq[kb * 256 + c]       * QS2;
            v1 = gq[kb + 1] * Wq[(kb + 1) * 256 + c] * QS2;
            v2 = gq[kb + 8] * Wq[(kb + 8) * 256 + c] * QS2;
            v3 = gq[kb + 9] * Wq[(kb + 9) * 256 + c] * QS2;
        } else if (mat == 1) {
            const float* gkv = br ? gkv1 : gkv0;
            const float* Wk = br ? Wk1 : Wk0; const float* Wv = br ? Wv1 : Wv0;
            const float* Wm = (c < 128) ? Wk : Wv;
            int cc = c & 127;
            v0 = gkv[kb]     * Wm[kb * 128 + cc];
            v1 = gkv[kb + 1] * Wm[(kb + 1) * 128 + cc];
            v2 = gkv[kb + 8] * Wm[(kb + 8) * 128 + cc];
            v3 = gkv[kb + 9] * Wm[(kb + 9) * 128 + cc];
        } else {
            const float* Wo = br ? Wo1 : Wo0;
            v0 = Wo[kb * 256 + c];
            v1 = Wo[(kb + 1) * 256 + c];
            v2 = Wo[(kb + 8) * 256 + c];
            v3 = Wo[(kb + 9) * 256 + c];
        }
        uint2 pk;
        pk.x = h2u(v0, v1);
        pk.y = h2u(v2, v3);
        uint2* dst = (mat == 0) ? g_Wq[br] : (mat == 1) ? g_Wkv[br] : g_Wo[br];
        dst[fid * 32 + lane] = pk;
    } else if (gid < 106496) {
        // bias: 8 threads per output, 32 elements each, shfl-reduced in 8-lane groups
        int t8 = gid - 98304;       // 0..8191
        int t = t8 >> 3;            // output 0..1023
        int sub = t8 & 7;           // 8-way k split
        int br = t >> 9, tt = t & 511;
        const float* bqn = br ? bqn1 : bqn0; const float* bkvn = br ? bkvn1 : bkvn0;
        const float* Wq = br ? Wq1 : Wq0; const float* Wk = br ? Wk1 : Wk0;
        const float* Wv = br ? Wv1 : Wv0;
        const float* bq = br ? bq1 : bq0; const float* bk = br ? bk1 : bk0;
        const float* bv = br ? bv1 : bv0;
        int k0 = sub * 32;
        float a = 0.0f;
        if (tt < 256) {
#pragma unroll 8
            for (int k = k0; k < k0 + 32; ++k) a += bqn[k] * Wq[k * 256 + tt];
        } else if (tt < 384) {
            int cc = tt - 256;
#pragma unroll 8
            for (int k = k0; k < k0 + 32; ++k) a += bkvn[k] * Wk[k * 128 + cc];
        } else {
            int cc = tt - 384;
#pragma unroll 8
            for (int k = k0; k < k0 + 32; ++k) a += bkvn[k] * Wv[k * 128 + cc];
        }
        a += __shfl_xor_sync(0xffffffffu, a, 1);
        a += __shfl_xor_sync(0xffffffffu, a, 2);
        a += __shfl_xor_sync(0xffffffffu, a, 4);
        if (sub == 0) {
            if (tt < 256)      g_bq[br][tt] = (a + bq[tt]) * QS2;
            else if (tt < 384) g_bkv[br][tt - 256] = a + bk[tt - 256];
            else               g_bkv[br][tt - 256] = a + bv[tt - 384];
        }
    }
}

// ---------------- main fused kernel: 1 CTA = 1 sequence, 1 branch -------------------
__global__ void __launch_bounds__(256, 2)
fusion_kernel(const float* __restrict__ xspec, const float* __restrict__ xspat,
              const float* __restrict__ bo0, const float* __restrict__ bo1,
              const float* __restrict__ gate0, const float* __restrict__ gate1,
              float* __restrict__ out) {
    extern __shared__ char smc[];
    __half* buf1 = reinterpret_cast<__half*>(smc + BUF1_OFF);
    __half* buf2 = reinterpret_cast<__half*>(smc + BUF2_OFF);

    int tid = threadIdx.x, w = tid >> 5, lane = tid & 31;
    int br = blockIdx.x & 1;              // interleaved: CTA pairs share x tiles in L2
    int bc = blockIdx.x >> 1;
    int b = bc >> 7, c = bc & 127;
    int cbase = (b * 8192 + c) * 256;

    const float* xq  = br ? xspat : xspec;
    const float* xkv = br ? xspec : xspat;
    const float* bo  = br ? bo1 : bo0;
    float gv = br ? gate1[0] : gate0[0];
    float sg = 1.0f / (1.0f + __expf(-gv));
    float* outb = out + (br ? OUT_HALF : 0);

    // ---------- LN: 64 rows -> half buffer ----------
    auto ln_rows = [&](__half* dst, const float* __restrict__ src) {
        for (int r = w; r < 64; r += 8) {
            const float* rp = src + cbase + r * 32768;
            float4 u = *reinterpret_cast<const float4*>(rp + lane * 8);
            float4 v = *reinterpret_cast<const float4*>(rp + lane * 8 + 4);
            float s = u.x + u.y + u.z + u.w + v.x + v.y + v.z + v.w;
            float q = u.x * u.x + u.y * u.y + u.z * u.z + u.w * u.w +
                      v.x * v.x + v.y * v.y + v.z * v.z + v.w * v.w;
#pragma unroll
            for (int o = 16; o; o >>= 1) {
                s += __shfl_xor_sync(0xffffffffu, s, o);
                q += __shfl_xor_sync(0xffffffffu, q, o);
            }
            float mu = s * (1.0f / 256.0f);
            float rs = rsqrtf(q * (1.0f / 256.0f) - mu * mu + 1e-5f);
            uint4 pk;
            uint32_t* ph = reinterpret_cast<uint32_t*>(&pk);
            ph[0] = h2u((u.x - mu) * rs, (u.y - mu) * rs);
            ph[1] = h2u((u.z - mu) * rs, (u.w - mu) * rs);
            ph[2] = h2u((v.x - mu) * rs, (v.y - mu) * rs);
            ph[3] = h2u((v.z - mu) * rs, (v.w - mu) * rs);
            *reinterpret_cast<uint4*>(dst + r * LDH + lane * 8) = pk;
        }
    };

    // ---------- GEMM: C[64x256] = A @ W + bias; B streamed from L2 (frag-major) -----
    auto gemm64 = [&](const __half* Abuf, const uint2* __restrict__ WF,
                      const float* __restrict__ bias, __half* dsth, int MODE) {
        int m0 = (w & 1) * 32, n0 = (w >> 1) * 64;
        int l15 = lane & 15, lhi = (lane >> 4) * 8;
        uint32_t aBase = smem_u32(Abuf) + ((m0 + l15) * LDH + lhi) * 2;
        const uint2* Wl = WF + (w >> 1) * 8 * 32 + lane;   // frag(n8 base) + lane

        float acc[16][4];
#pragma unroll
        for (int i = 0; i < 16; ++i)
#pragma unroll
            for (int j = 0; j < 4; ++j) acc[i][j] = 0.0f;

        uint2 B[2][8];
#pragma unroll
        for (int i = 0; i < 8; ++i) B[0][i] = Wl[i * 32];

#pragma unroll
        for (int k16 = 0; k16 < 16; ++k16) {
            const int cur = k16 & 1, nxt = cur ^ 1;
            if (k16 < 15) {
#pragma unroll
                for (int i = 0; i < 8; ++i)
                    B[nxt][i] = Wl[(k16 + 1) * 1024 + i * 32];
            }
            uint32_t a0[4], a1[4];
            uint32_t ak = aBase + (k16 * 16) * 2;
            ldsm4(a0, ak);
            ldsm4(a1, ak + 16 * LDH * 2);
#pragma unroll
            for (int ng = 0; ng < 4; ++ng) {
                mma16816(acc[ng * 2],     a0, B[cur][2 * ng].x,     B[cur][2 * ng].y);
                mma16816(acc[ng * 2 + 1], a0, B[cur][2 * ng + 1].x, B[cur][2 * ng + 1].y);
                mma16816(acc[8 + ng * 2],     a1, B[cur][2 * ng].x,     B[cur][2 * ng].y);
                mma16816(acc[8 + ng * 2 + 1], a1, B[cur][2 * ng + 1].x, B[cur][2 * ng + 1].y);
            }
        }
        if (MODE == 0) __syncthreads();   // in-place hazard only when writing smem

        int g = lane >> 2, c2 = (lane & 3) * 2;
        if (MODE == 0) {
#pragma unroll
            for (int nt = 0; nt < 8; ++nt) {
                int col = n0 + nt * 8 + c2;
                float2 bb = *reinterpret_cast<const float2*>(bias + col);
#pragma unroll
                for (int mi = 0; mi < 2; ++mi) {
                    float* a4 = acc[mi * 8 + nt];
                    uint32_t h0 = h2u(a4[0] + bb.x, a4[1] + bb.y);
                    uint32_t h1 = h2u(a4[2] + bb.x, a4[3] + bb.y);
                    *reinterpret_cast<uint32_t*>(dsth + (m0 + mi * 16 + g) * LDH + col) = h0;
                    *reinterpret_cast<uint32_t*>(dsth + (m0 + mi * 16 + 8 + g) * LDH + col) = h1;
                }
            }
            __syncthreads();
        } else {
#pragma unroll
            for (int nt = 0; nt < 8; ++nt) {
                int col = n0 + nt * 8 + c2;
                float2 bb = *reinterpret_cast<const float2*>(bias + col);
#pragma unroll
                for (int mi = 0; mi < 2; ++mi) {
                    float* a4 = acc[mi * 8 + nt];
#pragma unroll
                    for (int hrow = 0; hrow < 2; ++hrow) {
                        int row = m0 + mi * 16 + hrow * 8 + g;
                        int off = cbase + row * 32768 + col;
                        float2 x = *reinterpret_cast<const float2*>(xq + off);
                        float2 o;
                        o.x = x.x + sg * (a4[hrow * 2 + 0] + bb.x);
                        o.y = x.y + sg * (a4[hrow * 2 + 1] + bb.y);
                        *reinterpret_cast<float2*>(outb + off) = o;
                    }
                }
            }
        }
    };

    // ================= pipeline =================
    ln_rows(buf1, xkv);
    ln_rows(buf2, xq);
    __syncthreads();
    gemm64(buf1, g_Wkv[br], g_bkv[br], buf1, 0);
    gemm64(buf2, g_Wq[br], g_bq[br], buf2, 0);

    // ===== attention: K/V frags shared across each query-head pair; AO over Q_h =====
    {
        int rows0 = (w & 3) * 16;
        int l15 = lane & 15, lhi = (lane >> 4) * 8;
        int g = lane >> 2, c2 = (lane & 3) * 2;
        uint32_t q_base = smem_u32(buf2) + ((rows0 + l15) * LDH + lhi) * 2;
        uint32_t k_base = smem_u32(buf1) + (l15 * LDH + lhi) * 2;

#pragma unroll
        for (int hpi = 0; hpi < 2; ++hpi) {
            int hp = (w >> 2) * 2 + hpi;           // kv head 0..3
            int ko = hp * 32, vo = 128 + hp * 32;
            uint32_t kr[4][2][4];
#pragma unroll
            for (int tb = 0; tb < 4; ++tb)
#pragma unroll
                for (int db = 0; db < 2; ++db)
                    ldsm4(kr[tb][db], k_base + (tb * 16 * LDH + ko + db * 16) * 2);

            uint32_t aP[2][4][4];
#pragma unroll
            for (int qh = 0; qh < 2; ++qh) {
                int qo = (hp * 2 + qh) * 32;
                uint32_t aQ[2][4];
                ldsm4(aQ[0], q_base + qo * 2);
                ldsm4(aQ[1], q_base + (qo + 16) * 2);
                float sc[8][4];
#pragma unroll
                for (int i = 0; i < 8; ++i)
#pragma unroll
                    for (int j = 0; j < 4; ++j) sc[i][j] = 0.0f;
#pragma unroll
                for (int tb = 0; tb < 4; ++tb)
#pragma unroll
                    for (int db = 0; db < 2; ++db) {
                        mma16816(sc[2 * tb],     aQ[db], kr[tb][db][0], kr[tb][db][2]);
                        mma16816(sc[2 * tb + 1], aQ[db], kr[tb][db][1], kr[tb][db][3]);
                    }
                float mx0 = -3.4e38f, mx1 = -3.4e38f;
#pragma unroll
                for (int nt = 0; nt < 8; ++nt) {
                    mx0 = fmaxf(mx0, fmaxf(sc[nt][0], sc[nt][1]));
                    mx1 = fmaxf(mx1, fmaxf(sc[nt][2], sc[nt][3]));
                }
                mx0 = fmaxf(mx0, __shfl_xor_sync(0xffffffffu, mx0, 1));
                mx0 = fmaxf(mx0, __shfl_xor_sync(0xffffffffu, mx0, 2));
                mx1 = fmaxf(mx1, __shfl_xor_sync(0xffffffffu, mx1, 1));
                mx1 = fmaxf(mx1, __shfl_xor_sync(0xffffffffu, mx1, 2));
                float s0 = 0.0f, s1 = 0.0f;
#pragma unroll
                for (int nt = 0; nt < 8; ++nt) {
                    sc[nt][0] = ex2f(sc[nt][0] - mx0); s0 += sc[nt][0];
                    sc[nt][1] = ex2f(sc[nt][1] - mx0); s0 += sc[nt][1];
                    sc[nt][2] = ex2f(sc[nt][2] - mx1); s1 += sc[nt][2];
                    sc[nt][3] = ex2f(sc[nt][3] - mx1); s1 += sc[nt][3];
                }
                s0 += __shfl_xor_sync(0xffffffffu, s0, 1);
                s0 += __shfl_xor_sync(0xffffffffu, s0, 2);
                s1 += __shfl_xor_sync(0xffffffffu, s1, 1);
                s1 += __shfl_xor_sync(0xffffffffu, s1, 2);
                float i0 = 1.0f / s0, i1 = 1.0f / s1;
#pragma unroll
                for (int kf = 0; kf < 4; ++kf) {
                    float* p0 = sc[2 * kf];
                    float* p1 = sc[2 * kf + 1];
                    aP[qh][kf][0] = h2u(p0[0] * i0, p0[1] * i0);
                    aP[qh][kf][1] = h2u(p0[2] * i1, p0[3] * i1);
                    aP[qh][kf][2] = h2u(p1[0] * i0, p1[1] * i0);
                    aP[qh][kf][3] = h2u(p1[2] * i1, p1[3] * i1);
                }
            }
            uint32_t vr[4][2][4];
#pragma unroll
            for (int tb = 0; tb < 4; ++tb)
#pragma unroll
                for (int db = 0; db < 2; ++db)
                    ldsm4t(vr[tb][db], k_base + (tb * 16 * LDH + vo + db * 16) * 2);
#pragma unroll
            for (int qh = 0; qh < 2; ++qh) {
                int qo = (hp * 2 + qh) * 32;
                float ao[4][4];
#pragma unroll
                for (int i = 0; i < 4; ++i)
#pragma unroll
                    for (int j = 0; j < 4; ++j) ao[i][j] = 0.0f;
#pragma unroll
                for (int kb = 0; kb < 4; ++kb)
#pragma unroll
                    for (int db = 0; db < 2; ++db) {
                        mma16816(ao[2 * db],     aP[qh][kb], vr[kb][db][0], vr[kb][db][1]);
                        mma16816(ao[2 * db + 1], aP[qh][kb], vr[kb][db][2], vr[kb][db][3]);
                    }
#pragma unroll
                for (int dn = 0; dn < 4; ++dn) {
                    int col = qo + dn * 8 + c2;
                    *reinterpret_cast<uint32_t*>(buf2 + (rows0 + g) * LDH + col) =
                        h2u(ao[dn][0], ao[dn][1]);
                    *reinterpret_cast<uint32_t*>(buf2 + (rows0 + 8 + g) * LDH + col) =
                        h2u(ao[dn][2], ao[dn][3]);
                }
            }
        }
    }
    __syncthreads();

    // ================= O projection + residual epilogue =================
    gemm64(buf2, g_Wo[br], bo, nullptr, 1);
}

// ---------------- host launcher -------------------------------------------------------
extern "C" void kernel_launch(void* const* d_in, const int* in_sizes, int n_in,
                              void* d_out, int out_size) {
    const float* xspec = (const float*)d_in[0];
    const float* xspat = (const float*)d_in[1];
    const float* lsqg  = (const float*)d_in[2];
    const float* lsqb  = (const float*)d_in[3];
    const float* lskvg = (const float*)d_in[4];
    const float* lskvb = (const float*)d_in[5];
    const float* ltqg  = (const float*)d_in[6];
    const float* ltqb  = (const float*)d_in[7];
    const float* ltkvg = (const float*)d_in[8];
    const float* ltkvb = (const float*)d_in[9];
    const float* Wq0 = (const float*)d_in[10]; const float* bq0 = (const float*)d_in[11];
    const float* Wk0 = (const float*)d_in[12]; const float* bk0 = (const float*)d_in[13];
    const float* Wv0 = (const float*)d_in[14]; const float* bv0 = (const float*)d_in[15];
    const float* Wo0 = (const float*)d_in[16]; const float* bo0 = (const float*)d_in[17];
    const float* Wq1 = (const float*)d_in[18]; const float* bq1 = (const float*)d_in[19];
    const float* Wk1 = (const float*)d_in[20]; const float* bk1 = (const float*)d_in[21];
    const float* Wv1 = (const float*)d_in[22]; const float* bv1 = (const float*)d_in[23];
    const float* Wo1 = (const float*)d_in[24]; const float* bo1 = (const float*)d_in[25];
    const float* g0  = (const float*)d_in[26];
    const float* g1  = (const float*)d_in[27];
    float* out = (float*)d_out;

    // branch 0 (s2t): q-norm=spec_q, kv-norm=spat_kv; branch 1 (t2s): q-norm=spat_q, kv-norm=spec_kv
    prep_all<<<416, 256>>>(lsqg, ltkvg, ltqg, lskvg,
                           lsqb, ltkvb, ltqb, lskvb,
                           Wq0, bq0, Wk0, bk0, Wv0, bv0, Wo0,
                           Wq1, bq1, Wk1, bk1, Wv1, bv1, Wo1);

    cudaFuncSetAttribute(fusion_kernel, cudaFuncAttributeMaxDynamicSharedMemorySize, SMEM_BYTES);
    fusion_kernel<<<2048, 256, SMEM_BYTES>>>(xspec, xspat, bo0, bo1, g0, g1, out);
}